// round 1
// baseline (speedup 1.0000x reference)
#include <cuda_runtime.h>

// ApplyDF: complex order-5 time-FIR on first 96 of 481 freq bins, copy the rest.
// spec:  [B=32][1][T=2000][F=481][2]  float32
// coefs: [B=32][ORDER=5][T=2000][NB=96][2] float32
// out:   same as spec
//
// out[b,0,t,f] (f<96) = sum_{n=0..4} spec[b,0,t+n-4,f] * coefs[b,n,t,f]   (complex mul)
// with zero padding for t+n-4 < 0.

#define BB 32
#define TT 2000
#define FF 481
#define NB 96
#define ORD 5

__global__ __launch_bounds__(256) void apply_df_kernel(
    const float2* __restrict__ spec,
    const float2* __restrict__ coefs,
    float2* __restrict__ out)
{
    const int f  = blockIdx.x * blockDim.x + threadIdx.x;
    if (f >= FF) return;
    const int bt = blockIdx.y;            // b*T + t  (64000 blocks in y)
    const int t  = bt % TT;
    const int b  = bt / TT;

    const long base = (long)bt * FF + f;  // element index into spec/out (float2 units)
    const float2 s_cur = spec[base];      // tap n=4 (always valid) / copy value

    if (f >= NB) {
        out[base] = s_cur;
        return;
    }

    // coefs element index for (b, n=0, t, f)
    const float2* __restrict__ cptr = coefs + (((long)b * ORD) * TT + t) * NB + f;
    const long c_nstride = (long)TT * NB;         // stride between taps n
    const long s_tstride = (long)FF;              // stride between times t

    float outr = 0.0f, outi = 0.0f;

    #pragma unroll
    for (int n = 0; n < ORD; ++n) {
        const int ts = t + n - (ORD - 1);
        float2 sv;
        if (n == ORD - 1) {
            sv = s_cur;
        } else if (ts >= 0) {
            sv = spec[base + (long)(n - (ORD - 1)) * s_tstride];
        } else {
            sv = make_float2(0.0f, 0.0f);
        }
        const float2 c = cptr[(long)n * c_nstride];
        outr = fmaf(sv.x, c.x, fmaf(-sv.y, c.y, outr));
        outi = fmaf(sv.x, c.y, fmaf( sv.y, c.x, outi));
    }

    out[base] = make_float2(outr, outi);
}

extern "C" void kernel_launch(void* const* d_in, const int* in_sizes, int n_in,
                              void* d_out, int out_size)
{
    const float2* spec  = (const float2*)d_in[0];
    const float2* coefs = (const float2*)d_in[1];
    float2* out = (float2*)d_out;

    dim3 block(256, 1, 1);
    dim3 grid((FF + 255) / 256, BB * TT, 1);   // (2, 64000)
    apply_df_kernel<<<grid, block>>>(spec, coefs, out);
}

// round 2
// speedup vs baseline: 1.0107x; 1.0107x over previous
#include <cuda_runtime.h>

// ApplyDF: complex order-5 time-FIR on first 96 of 481 freq bins, copy the rest.
// spec:  [B=32][1][T=2000][F=481][2]  float32
// coefs: [B=32][ORDER=5][T=2000][NB=96][2] float32
// out:   same shape as spec
//
// out[b,0,t,f] (f<96) = sum_{n=0..4} spec[b,0,t+n-4,f] * coefs[b,n,t,f]   (complex mul)
// zero padding for t+n-4 < 0.  f>=96: straight copy.
//
// All indexing 32-bit: max element index 32*2000*481 = 30.8M (< 2^31),
// max byte offset ~246 MB (< 2^31).

#define BB 32
#define TT 2000
#define FF 481
#define NB 96
#define ORD 5

__global__ __launch_bounds__(256) void apply_df_kernel(
    const float2* __restrict__ spec,
    const float2* __restrict__ coefs,
    float2* __restrict__ out)
{
    const int f = blockIdx.x * 256 + threadIdx.x;
    if (f >= FF) return;
    const int t = blockIdx.y;
    const int b = blockIdx.z;

    const int base = (b * TT + t) * FF + f;      // float2 element index
    const float2 s_cur = __ldg(&spec[base]);     // tap n=4 / copy value

    if (f >= NB) {
        out[base] = s_cur;
        return;
    }

    // Load the 4 history taps (n = 0..3 -> t offsets -4..-1), zero-padded.
    float2 s0, s1, s2, s3;
    s0 = (t >= 4) ? __ldg(&spec[base - 4 * FF]) : make_float2(0.f, 0.f);
    s1 = (t >= 3) ? __ldg(&spec[base - 3 * FF]) : make_float2(0.f, 0.f);
    s2 = (t >= 2) ? __ldg(&spec[base - 2 * FF]) : make_float2(0.f, 0.f);
    s3 = (t >= 1) ? __ldg(&spec[base - 1 * FF]) : make_float2(0.f, 0.f);

    // coefs element index for (b, n, t, f): ((b*5 + n)*TT + t)*NB + f
    const int cbase = ((b * ORD) * TT + t) * NB + f;
    const int cstr  = TT * NB;                   // tap stride
    const float2 c0 = __ldg(&coefs[cbase]);
    const float2 c1 = __ldg(&coefs[cbase + cstr]);
    const float2 c2 = __ldg(&coefs[cbase + 2 * cstr]);
    const float2 c3 = __ldg(&coefs[cbase + 3 * cstr]);
    const float2 c4 = __ldg(&coefs[cbase + 4 * cstr]);

    float outr, outi;
    outr = fmaf(s0.x, c0.x, -s0.y * c0.y);
    outi = fmaf(s0.x, c0.y,  s0.y * c0.x);
    outr = fmaf(s1.x, c1.x, fmaf(-s1.y, c1.y, outr));
    outi = fmaf(s1.x, c1.y, fmaf( s1.y, c1.x, outi));
    outr = fmaf(s2.x, c2.x, fmaf(-s2.y, c2.y, outr));
    outi = fmaf(s2.x, c2.y, fmaf( s2.y, c2.x, outi));
    outr = fmaf(s3.x, c3.x, fmaf(-s3.y, c3.y, outr));
    outi = fmaf(s3.x, c3.y, fmaf( s3.y, c3.x, outi));
    outr = fmaf(s_cur.x, c4.x, fmaf(-s_cur.y, c4.y, outr));
    outi = fmaf(s_cur.x, c4.y, fmaf( s_cur.y, c4.x, outi));

    out[base] = make_float2(outr, outi);
}

extern "C" void kernel_launch(void* const* d_in, const int* in_sizes, int n_in,
                              void* d_out, int out_size)
{
    const float2* spec  = (const float2*)d_in[0];
    const float2* coefs = (const float2*)d_in[1];
    float2* out = (float2*)d_out;

    dim3 block(256, 1, 1);
    dim3 grid((FF + 255) / 256, TT, BB);   // (2, 2000, 32)
    apply_df_kernel<<<grid, block>>>(spec, coefs, out);
}

// round 3
// speedup vs baseline: 1.2308x; 1.2177x over previous
#include <cuda_runtime.h>

// ApplyDF: complex order-5 time-FIR on first 96 of 481 freq bins, copy the rest.
// spec:  [B=32][1][T=2000][F=481][2]  float32
// coefs: [B=32][ORDER=5][T=2000][NB=96][2] float32
// out:   same shape as spec
//
// Each thread processes TWO consecutive time steps (t0, t0+1) for one f:
//  - filter (f<96): 6 spec taps (windows overlap by 4) + 10 coefs, 2 stores
//  - copy  (f>=96): 2 independent load/store pairs
// This doubles per-thread memory-level parallelism to push HBM utilization.
//
// All indexing 32-bit (max byte offset ~246 MB < 2^31).

#define BB 32
#define TT 2000
#define FF 481
#define NB 96
#define ORD 5

__device__ __forceinline__ void cmac(float2 s, float2 c, float& r, float& i) {
    r = fmaf(s.x, c.x, fmaf(-s.y, c.y, r));
    i = fmaf(s.x, c.y, fmaf( s.y, c.x, i));
}

__global__ __launch_bounds__(256) void apply_df_kernel(
    const float2* __restrict__ spec,
    const float2* __restrict__ coefs,
    float2* __restrict__ out)
{
    const int f = blockIdx.x * 256 + threadIdx.x;
    if (f >= FF) return;
    const int t0 = blockIdx.y * 2;          // TT=2000 even, t0+1 always valid
    const int b  = blockIdx.z;

    const int base0 = (b * TT + t0) * FF + f;   // float2 element index, time t0
    const int base1 = base0 + FF;               // time t0+1

    const float2 sA = __ldg(&spec[base0]);      // tap at t0   / copy value 0
    const float2 sB = __ldg(&spec[base1]);      // tap at t0+1 / copy value 1

    if (f >= NB) {
        out[base0] = sA;
        out[base1] = sB;
        return;
    }

    const float2 z = make_float2(0.f, 0.f);
    // History taps t0-4 .. t0-1 (zero-padded at sequence start)
    const float2 sm4 = (t0 >= 4) ? __ldg(&spec[base0 - 4 * FF]) : z;
    const float2 sm3 = (t0 >= 3) ? __ldg(&spec[base0 - 3 * FF]) : z;
    const float2 sm2 = (t0 >= 2) ? __ldg(&spec[base0 - 2 * FF]) : z;
    const float2 sm1 = (t0 >= 1) ? __ldg(&spec[base0 - 1 * FF]) : z;

    // coefs element index for (b, n, t, f): ((b*5 + n)*TT + t)*NB + f
    const int cb0  = ((b * ORD) * TT + t0) * NB + f;   // (b, n=0, t0,   f)
    const int cb1  = cb0 + NB;                         // (b, n=0, t0+1, f)
    const int cstr = TT * NB;                          // tap stride

    const float2 c00 = __ldg(&coefs[cb0]);
    const float2 c01 = __ldg(&coefs[cb0 + cstr]);
    const float2 c02 = __ldg(&coefs[cb0 + 2 * cstr]);
    const float2 c03 = __ldg(&coefs[cb0 + 3 * cstr]);
    const float2 c04 = __ldg(&coefs[cb0 + 4 * cstr]);
    const float2 c10 = __ldg(&coefs[cb1]);
    const float2 c11 = __ldg(&coefs[cb1 + cstr]);
    const float2 c12 = __ldg(&coefs[cb1 + 2 * cstr]);
    const float2 c13 = __ldg(&coefs[cb1 + 3 * cstr]);
    const float2 c14 = __ldg(&coefs[cb1 + 4 * cstr]);

    // Output at t0: taps (t0-4..t0) x coefs(t0, n=0..4)
    float r0 = 0.f, i0 = 0.f;
    cmac(sm4, c00, r0, i0);
    cmac(sm3, c01, r0, i0);
    cmac(sm2, c02, r0, i0);
    cmac(sm1, c03, r0, i0);
    cmac(sA,  c04, r0, i0);

    // Output at t0+1: taps (t0-3..t0+1) x coefs(t0+1, n=0..4)
    float r1 = 0.f, i1 = 0.f;
    cmac(sm3, c10, r1, i1);
    cmac(sm2, c11, r1, i1);
    cmac(sm1, c12, r1, i1);
    cmac(sA,  c13, r1, i1);
    cmac(sB,  c14, r1, i1);

    out[base0] = make_float2(r0, i0);
    out[base1] = make_float2(r1, i1);
}

extern "C" void kernel_launch(void* const* d_in, const int* in_sizes, int n_in,
                              void* d_out, int out_size)
{
    const float2* spec  = (const float2*)d_in[0];
    const float2* coefs = (const float2*)d_in[1];
    float2* out = (float2*)d_out;

    dim3 block(256, 1, 1);
    dim3 grid((FF + 255) / 256, TT / 2, BB);   // (2, 1000, 32)
    apply_df_kernel<<<grid, block>>>(spec, coefs, out);
}

// round 4
// speedup vs baseline: 1.2768x; 1.0374x over previous
#include <cuda_runtime.h>

// ApplyDF: complex order-5 time-FIR on first 96 of 481 freq bins, copy the rest.
// spec:  [B=32][1][T=2000][F=481][2]  float32
// coefs: [B=32][ORDER=5][T=2000][NB=96][2] float32
// out:   same shape as spec
//
// Each thread processes FOUR consecutive time steps (t0..t0+3) for one f:
//  - filter (f<96): 8 spec taps (windows overlap) + 20 coefs, 4 stores
//  - copy  (f>=96): 4 independent load/store pairs
// Maximizes per-thread memory-level parallelism to saturate HBM.
//
// All indexing 32-bit (max byte offset ~246 MB < 2^31).

#define BB 32
#define TT 2000
#define FF 481
#define NB 96
#define ORD 5

__device__ __forceinline__ void cmac(float2 s, float2 c, float& r, float& i) {
    r = fmaf(s.x, c.x, fmaf(-s.y, c.y, r));
    i = fmaf(s.x, c.y, fmaf( s.y, c.x, i));
}

__global__ __launch_bounds__(256) void apply_df_kernel(
    const float2* __restrict__ spec,
    const float2* __restrict__ coefs,
    float2* __restrict__ out)
{
    const int f = blockIdx.x * 256 + threadIdx.x;
    if (f >= FF) return;
    const int t0 = blockIdx.y * 4;          // TT=2000 divisible by 4
    const int b  = blockIdx.z;

    const int base0 = (b * TT + t0) * FF + f;   // float2 element index @ t0

    // Current + future taps (t0..t0+3): always in range.
    const float2 sA = __ldg(&spec[base0]);
    const float2 sB = __ldg(&spec[base0 + FF]);
    const float2 sC = __ldg(&spec[base0 + 2 * FF]);
    const float2 sD = __ldg(&spec[base0 + 3 * FF]);

    if (f >= NB) {
        out[base0]          = sA;
        out[base0 + FF]     = sB;
        out[base0 + 2 * FF] = sC;
        out[base0 + 3 * FF] = sD;
        return;
    }

    const float2 z = make_float2(0.f, 0.f);
    // History taps t0-4 .. t0-1 (zero-padded at sequence start; only block y=0 pads)
    const float2 sm4 = (t0 >= 4) ? __ldg(&spec[base0 - 4 * FF]) : z;
    const float2 sm3 = (t0 >= 3) ? __ldg(&spec[base0 - 3 * FF]) : z;
    const float2 sm2 = (t0 >= 2) ? __ldg(&spec[base0 - 2 * FF]) : z;
    const float2 sm1 = (t0 >= 1) ? __ldg(&spec[base0 - 1 * FF]) : z;

    // coefs element index for (b, n, t, f): ((b*5 + n)*TT + t)*NB + f
    const int cb   = ((b * ORD) * TT + t0) * NB + f;   // (b, n=0, t0, f)
    const int cstr = TT * NB;                          // tap-n stride
    // time stride within coefs = NB

    float r0 = 0.f, i0 = 0.f, r1 = 0.f, i1 = 0.f;
    float r2 = 0.f, i2 = 0.f, r3 = 0.f, i3 = 0.f;

    // tap n=0 row: coef(t0+j, n=0) multiplies spec[t0+j-4]
    {
        const float2 c0 = __ldg(&coefs[cb]);
        const float2 c1 = __ldg(&coefs[cb + NB]);
        const float2 c2 = __ldg(&coefs[cb + 2 * NB]);
        const float2 c3 = __ldg(&coefs[cb + 3 * NB]);
        cmac(sm4, c0, r0, i0);
        cmac(sm3, c1, r1, i1);
        cmac(sm2, c2, r2, i2);
        cmac(sm1, c3, r3, i3);
    }
    // tap n=1: spec[t0+j-3]
    {
        const float2 c0 = __ldg(&coefs[cb + cstr]);
        const float2 c1 = __ldg(&coefs[cb + cstr + NB]);
        const float2 c2 = __ldg(&coefs[cb + cstr + 2 * NB]);
        const float2 c3 = __ldg(&coefs[cb + cstr + 3 * NB]);
        cmac(sm3, c0, r0, i0);
        cmac(sm2, c1, r1, i1);
        cmac(sm1, c2, r2, i2);
        cmac(sA,  c3, r3, i3);
    }
    // tap n=2: spec[t0+j-2]
    {
        const float2 c0 = __ldg(&coefs[cb + 2 * cstr]);
        const float2 c1 = __ldg(&coefs[cb + 2 * cstr + NB]);
        const float2 c2 = __ldg(&coefs[cb + 2 * cstr + 2 * NB]);
        const float2 c3 = __ldg(&coefs[cb + 2 * cstr + 3 * NB]);
        cmac(sm2, c0, r0, i0);
        cmac(sm1, c1, r1, i1);
        cmac(sA,  c2, r2, i2);
        cmac(sB,  c3, r3, i3);
    }
    // tap n=3: spec[t0+j-1]
    {
        const float2 c0 = __ldg(&coefs[cb + 3 * cstr]);
        const float2 c1 = __ldg(&coefs[cb + 3 * cstr + NB]);
        const float2 c2 = __ldg(&coefs[cb + 3 * cstr + 2 * NB]);
        const float2 c3 = __ldg(&coefs[cb + 3 * cstr + 3 * NB]);
        cmac(sm1, c0, r0, i0);
        cmac(sA,  c1, r1, i1);
        cmac(sB,  c2, r2, i2);
        cmac(sC,  c3, r3, i3);
    }
    // tap n=4: spec[t0+j]
    {
        const float2 c0 = __ldg(&coefs[cb + 4 * cstr]);
        const float2 c1 = __ldg(&coefs[cb + 4 * cstr + NB]);
        const float2 c2 = __ldg(&coefs[cb + 4 * cstr + 2 * NB]);
        const float2 c3 = __ldg(&coefs[cb + 4 * cstr + 3 * NB]);
        cmac(sA, c0, r0, i0);
        cmac(sB, c1, r1, i1);
        cmac(sC, c2, r2, i2);
        cmac(sD, c3, r3, i3);
    }

    out[base0]          = make_float2(r0, i0);
    out[base0 + FF]     = make_float2(r1, i1);
    out[base0 + 2 * FF] = make_float2(r2, i2);
    out[base0 + 3 * FF] = make_float2(r3, i3);
}

extern "C" void kernel_launch(void* const* d_in, const int* in_sizes, int n_in,
                              void* d_out, int out_size)
{
    const float2* spec  = (const float2*)d_in[0];
    const float2* coefs = (const float2*)d_in[1];
    float2* out = (float2*)d_out;

    dim3 block(256, 1, 1);
    dim3 grid((FF + 255) / 256, TT / 4, BB);   // (2, 500, 32)
    apply_df_kernel<<<grid, block>>>(spec, coefs, out);
}